// round 7
// baseline (speedup 1.0000x reference)
#include <cuda_runtime.h>
#include <cuda_bf16.h>
#include <cstdint>

#define NN      64
#define HH      256
#define OO      64
#define MAXIT   30
#define TOLV    1e-7f

#define BTOT    262144
#define TB      256
#define ROWS    256          // samples per MMA block (two 16-row tiles per warp)

// ---- global weight blob layout (bytes), mirrored 1:1 into smem ----
#define GW_W1H  0                       // [256 rows][72 bf16] stride 144B
#define GW_W1L  (GW_W1H + 256*144)      // 36864
#define GW_W2H  (GW_W1L + 256*144)      // 73728  [64 rows][264 bf16] stride 528B
#define GW_W2L  (GW_W2H + 64*528)       // 107520
#define GW_B1   (GW_W2L + 64*528)       // 141312 b1[256] f32
#define GW_B2   (GW_B1 + 1024)          // 142336 b2[64] f32
#define GW_SIZE (GW_B2 + 256)           // 142592

// ---- MMA-kernel smem layout ----
#define SM_XH   0                       // [256 rows][72 bf16] stride 144B
#define SM_XL   (SM_XH + ROWS*144)      // 36864
#define SM_WB   (SM_XL + ROWS*144)      // 73728
#define SM_TOTAL (SM_WB + GW_SIZE)      // 216320 bytes (~211 KB)

__device__ __align__(16) unsigned char gWB[GW_SIZE];
__device__ __align__(16) unsigned char gXH[(size_t)BTOT * 128];   // bf16x2 rows, 128B each
__device__ __align__(16) unsigned char gXL[(size_t)BTOT * 128];
__device__ float ges[BTOT];

// pack two f32 -> bf16x2 (arg0 -> low half, arg1 -> high half)
__device__ __forceinline__ uint32_t pack_bf16x2(float lo, float hi) {
    uint32_t d;
    asm("cvt.rn.bf16x2.f32 %0, %1, %2;" : "=r"(d) : "f"(hi), "f"(lo));
    return d;
}
__device__ __forceinline__ void bf2_vals(uint32_t p, float& v0, float& v1) {
    v0 = __uint_as_float(p << 16);
    v1 = __uint_as_float(p & 0xffff0000u);
}
__device__ __forceinline__ void split2(float v0, float v1, uint32_t& hi, uint32_t& lo) {
    hi = pack_bf16x2(v0, v1);
    float h0, h1; bf2_vals(hi, h0, h1);
    lo = pack_bf16x2(v0 - h0, v1 - h1);
}
__device__ __forceinline__ void mma16816(float* c, const uint32_t* a, uint32_t b0, uint32_t b1) {
    asm volatile("mma.sync.aligned.m16n8k16.row.col.f32.bf16.bf16.f32 "
                 "{%0,%1,%2,%3}, {%4,%5,%6,%7}, {%8,%9}, {%0,%1,%2,%3};"
                 : "+f"(c[0]), "+f"(c[1]), "+f"(c[2]), "+f"(c[3])
                 : "r"(a[0]), "r"(a[1]), "r"(a[2]), "r"(a[3]), "r"(b0), "r"(b1));
}

// ============ kernel 1: one-time weight split into gWB ============
__global__ __launch_bounds__(256, 1)
void conv_kernel(const float* __restrict__ W1, const float* __restrict__ b1,
                 const float* __restrict__ W2, const float* __restrict__ b2)
{
    const int tid = threadIdx.x;
    #pragma unroll 4
    for (int p = tid; p < HH * NN / 2; p += 256) {
        int h  = p >> 5;
        int n2 = (p & 31) * 2;
        float2 w = *(const float2*)(W1 + h * NN + n2);
        uint32_t hi, lo; split2(w.x, w.y, hi, lo);
        *(uint32_t*)(gWB + GW_W1H + h * 144 + n2 * 2) = hi;
        *(uint32_t*)(gWB + GW_W1L + h * 144 + n2 * 2) = lo;
    }
    #pragma unroll 4
    for (int p = tid; p < OO * HH / 2; p += 256) {
        int o  = p >> 7;
        int k2 = (p & 127) * 2;
        float2 w = *(const float2*)(W2 + o * HH + k2);
        uint32_t hi, lo; split2(w.x, w.y, hi, lo);
        *(uint32_t*)(gWB + GW_W2H + o * 528 + k2 * 2) = hi;
        *(uint32_t*)(gWB + GW_W2L + o * 528 + k2 * 2) = lo;
    }
    ((float*)(gWB + GW_B1))[tid] = b1[tid];
    if (tid < OO) ((float*)(gWB + GW_B2))[tid] = b2[tid];
}

// ============ kernel 2: full-chip Newton solve + x_sphere split ============
__global__ __launch_bounds__(256, 2)
void solve_kernel(const float* __restrict__ x, const float* __restrict__ r)
{
    __shared__ float srr[NN];
    const int tid = threadIdx.x;
    if (tid < NN) srr[tid] = r[tid];
    __syncthreads();

    const size_t row = (size_t)blockIdx.x * 256 + tid;
    float xv[NN];
    const float4* xr = (const float4*)(x + row * NN);
    #pragma unroll
    for (int i = 0; i < NN / 4; i++) {
        float4 v = xr[i];
        xv[4*i] = v.x; xv[4*i+1] = v.y; xv[4*i+2] = v.z; xv[4*i+3] = v.w;
    }
    float s = 0.0f;
    #pragma unroll 1
    for (int it = 0; it < MAXIT; it++) {
        float m2s = -2.0f * s;
        float f0 = 0.0f, f1 = 0.0f, g0 = 0.0f, g1 = 0.0f;
        #pragma unroll
        for (int i = 0; i < NN; i += 2) {
            float r0 = srr[i], r1 = srr[i+1];
            float e0 = __expf(r0 * m2s), e1 = __expf(r1 * m2s);
            float p0 = e0 * xv[i] * xv[i], p1 = e1 * xv[i+1] * xv[i+1];
            f0 += p0;              f1 += p1;
            g0 = fmaf(r0, p0, g0); g1 = fmaf(r1, p1, g1);
        }
        float F = f0 + f1;
        float G = -2.0f * (g0 + g1);
        if (F < 1e-30f || G == 0.0f) break;       // all-zero row -> s = 0
        if (fabsf(F - 1.0f) < TOLV) break;        // ref's stop rule
        s -= __logf(F) * F / G;                   // Newton on ln F (monotone)
    }
    ges[row] = __expf(s);                         // NU = 1

    uint32_t hiw[NN/2], low[NN/2];
    #pragma unroll
    for (int i = 0; i < NN; i += 2) {
        float v0 = xv[i]   * __expf(-srr[i]   * s);
        float v1 = xv[i+1] * __expf(-srr[i+1] * s);
        split2(v0, v1, hiw[i >> 1], low[i >> 1]);
    }
    uint4* dH = (uint4*)(gXH + row * 128);
    uint4* dL = (uint4*)(gXL + row * 128);
    #pragma unroll
    for (int q = 0; q < 8; q++) {
        dH[q] = make_uint4(hiw[4*q], hiw[4*q+1], hiw[4*q+2], hiw[4*q+3]);
        dL[q] = make_uint4(low[4*q], low[4*q+1], low[4*q+2], low[4*q+3]);
    }
}

// ============ kernel 3: pure HMMA MLP ============
__global__ __launch_bounds__(TB, 1)
void mma_kernel(float* __restrict__ out)
{
    extern __shared__ char sm[];
    const char* WB = sm + SM_WB;
    const float* sb1 = (const float*)(WB + GW_B1);
    const float* sb2 = (const float*)(WB + GW_B2);

    const int tid  = threadIdx.x;
    const int wid  = tid >> 5;
    const int lane = tid & 31;
    const int g    = lane >> 2;
    const int t    = lane & 3;
    const size_t b0 = (size_t)blockIdx.x * ROWS;

    // ---- bulk copy of pre-split weights (linear, L2-resident) ----
    {
        const uint4* src = (const uint4*)gWB;
        uint4* dst = (uint4*)(sm + SM_WB);
        for (int p = tid; p < GW_SIZE / 16; p += TB) dst[p] = src[p];
    }
    // ---- copy X tiles with 144B padding (fully coalesced reads) ----
    {
        const uint4* sH = (const uint4*)(gXH + b0 * 128);
        const uint4* sL = (const uint4*)(gXL + b0 * 128);
        for (int p = tid; p < ROWS * 8; p += TB) {
            int rr = p >> 3, q = p & 7;
            *(uint4*)(sm + SM_XH + rr * 144 + q * 16) = sH[p];
            *(uint4*)(sm + SM_XL + rr * 144 + q * 16) = sL[p];
        }
    }
    __syncthreads();

    #pragma unroll 1
    for (int half = 0; half < 2; half++) {
        const int rowb = wid * 32 + half * 16;
        const char* XH = sm + SM_XH + (rowb + g) * 144;
        const char* XL = sm + SM_XL + (rowb + g) * 144;

        float C2[8][4];
        #pragma unroll
        for (int nt = 0; nt < 8; nt++)
            { C2[nt][0] = 0.f; C2[nt][1] = 0.f; C2[nt][2] = 0.f; C2[nt][3] = 0.f; }

        #pragma unroll 1
        for (int hc = 0; hc < 4; hc++) {
            // ===== layer 1 chunk =====
            float C1[8][4];
            #pragma unroll
            for (int nt = 0; nt < 8; nt++)
                { C1[nt][0] = 0.f; C1[nt][1] = 0.f; C1[nt][2] = 0.f; C1[nt][3] = 0.f; }

            #pragma unroll
            for (int ks = 0; ks < 4; ks++) {
                const int kb = (ks * 16 + t * 2) * 2;
                uint32_t ah[4], al[4];
                ah[0] = *(const uint32_t*)(XH + kb);
                ah[1] = *(const uint32_t*)(XH + 8 * 144 + kb);
                ah[2] = *(const uint32_t*)(XH + kb + 16);
                ah[3] = *(const uint32_t*)(XH + 8 * 144 + kb + 16);
                al[0] = *(const uint32_t*)(XL + kb);
                al[1] = *(const uint32_t*)(XL + 8 * 144 + kb);
                al[2] = *(const uint32_t*)(XL + kb + 16);
                al[3] = *(const uint32_t*)(XL + 8 * 144 + kb + 16);
                #pragma unroll
                for (int nt = 0; nt < 8; nt++) {
                    const int n = hc * 64 + nt * 8 + g;
                    uint32_t bh0 = *(const uint32_t*)(WB + GW_W1H + n * 144 + kb);
                    uint32_t bh1 = *(const uint32_t*)(WB + GW_W1H + n * 144 + kb + 16);
                    uint32_t bl0 = *(const uint32_t*)(WB + GW_W1L + n * 144 + kb);
                    uint32_t bl1 = *(const uint32_t*)(WB + GW_W1L + n * 144 + kb + 16);
                    mma16816(C1[nt], ah, bh0, bh1);
                    mma16816(C1[nt], ah, bl0, bl1);
                    mma16816(C1[nt], al, bh0, bh1);
                }
            }

            // ===== epilogue 1 (registers): +b1, relu, bf16 split =====
            uint32_t a2h[4][4], a2l[4][4];
            #pragma unroll
            for (int nt = 0; nt < 8; nt++) {
                const int colb = hc * 64 + nt * 8 + t * 2;
                float bb0 = sb1[colb], bb1 = sb1[colb + 1];
                float v0 = fmaxf(C1[nt][0] + bb0, 0.0f);
                float v1 = fmaxf(C1[nt][1] + bb1, 0.0f);
                float v2 = fmaxf(C1[nt][2] + bb0, 0.0f);
                float v3 = fmaxf(C1[nt][3] + bb1, 0.0f);
                const int ks = nt >> 1, q = (nt & 1) * 2;
                split2(v0, v1, a2h[ks][q],     a2l[ks][q]);
                split2(v2, v3, a2h[ks][q + 1], a2l[ks][q + 1]);
            }

            // ===== layer 2 chunk =====
            #pragma unroll
            for (int ks = 0; ks < 4; ks++) {
                const int kb = (hc * 64 + ks * 16 + t * 2) * 2;
                #pragma unroll
                for (int nt = 0; nt < 8; nt++) {
                    const int n = nt * 8 + g;
                    uint32_t bh0 = *(const uint32_t*)(WB + GW_W2H + n * 528 + kb);
                    uint32_t bh1 = *(const uint32_t*)(WB + GW_W2H + n * 528 + kb + 16);
                    uint32_t bl0 = *(const uint32_t*)(WB + GW_W2L + n * 528 + kb);
                    uint32_t bl1 = *(const uint32_t*)(WB + GW_W2L + n * 528 + kb + 16);
                    mma16816(C2[nt], a2h[ks], bh0, bh1);
                    mma16816(C2[nt], a2h[ks], bl0, bl1);
                    mma16816(C2[nt], a2l[ks], bh0, bh1);
                }
            }
        }

        // ---- epilogue 2: (+b2) * e^s ----
        const float es0 = ges[b0 + rowb + g];
        const float es1 = ges[b0 + rowb + g + 8];
        float* o0r = out + (b0 + rowb + g) * OO;
        float* o1r = out + (b0 + rowb + g + 8) * OO;
        #pragma unroll
        for (int nt = 0; nt < 8; nt++) {
            const int col = nt * 8 + t * 2;
            float bb0 = sb2[col], bb1 = sb2[col + 1];
            float2 u0, u1;
            u0.x = (C2[nt][0] + bb0) * es0;  u0.y = (C2[nt][1] + bb1) * es0;
            u1.x = (C2[nt][2] + bb0) * es1;  u1.y = (C2[nt][3] + bb1) * es1;
            *(float2*)(o0r + col) = u0;
            *(float2*)(o1r + col) = u1;
        }
    }
}

extern "C" void kernel_launch(void* const* d_in, const int* in_sizes, int n_in,
                              void* d_out, int out_size)
{
    const float* x  = (const float*)d_in[0];
    const float* r  = (const float*)d_in[1];
    const float* W1 = (const float*)d_in[2];
    const float* b1 = (const float*)d_in[3];
    const float* W2 = (const float*)d_in[4];
    const float* b2 = (const float*)d_in[5];
    float* out = (float*)d_out;

    const int B = in_sizes[0] / NN;          // 262144
    cudaFuncSetAttribute(mma_kernel,
                         cudaFuncAttributeMaxDynamicSharedMemorySize, SM_TOTAL);
    conv_kernel<<<1, 256>>>(W1, b1, W2, b2);
    solve_kernel<<<B / 256, 256>>>(x, r);
    mma_kernel<<<B / ROWS, TB, SM_TOTAL>>>(out);
}

// round 9
// speedup vs baseline: 1.4028x; 1.4028x over previous
#include <cuda_runtime.h>
#include <cuda_bf16.h>
#include <cstdint>

#define NN      64
#define HH      256
#define OO      64
#define MAXIT   30
#define TOLV    1e-7f

#define TB      256          // 8 warps
#define ROWS    256          // samples per block; each warp: two 16-row tiles

// ---- smem byte layout ----
// X   : [256 rows][72 bf16] hi/lo   stride 144B (36 words ≡ 4 mod 32 -> LDSM conflict-free)
// W1  : [256 rows][72 bf16] hi/lo   row n = W1[n][0..63]
// W2  : [64 rows][264 bf16] hi/lo   row n = W2[n][0..255], stride 528B (132 ≡ 4)
#define SM_XH   0
#define SM_XL   (SM_XH + ROWS*144)        // 36864
#define SM_W1H  (SM_XL + ROWS*144)        // 73728
#define SM_W1L  (SM_W1H + 256*144)        // 110592
#define SM_W2H  (SM_W1L + 256*144)        // 147456
#define SM_W2L  (SM_W2H + 64*528)         // 181248
#define SM_RR   (SM_W2L + 64*528)         // 215040  r[64] f32
#define SM_B1   (SM_RR + 256)             // 215296  b1[256] f32
#define SM_B2   (SM_B1 + 1024)            // 216320  b2[64] f32
#define SM_ES   (SM_B2 + 256)             // 216576  es[256] f32
#define SM_TOTAL (SM_ES + 1024)           // 217600 bytes (~212.5 KB)

#define D_W1LO  (SM_W1L - SM_W1H)         // 36864
#define D_W2LO  (SM_W2L - SM_W2H)         // 33792

__device__ __forceinline__ uint32_t smem_u32(const void* p) {
    uint32_t a;
    asm("{ .reg .u64 t; cvta.to.shared.u64 t, %1; cvt.u32.u64 %0, t; }" : "=r"(a) : "l"(p));
    return a;
}
__device__ __forceinline__ uint32_t pack_bf16x2(float lo, float hi) {
    uint32_t d;
    asm("cvt.rn.bf16x2.f32 %0, %1, %2;" : "=r"(d) : "f"(hi), "f"(lo));
    return d;
}
__device__ __forceinline__ void bf2_vals(uint32_t p, float& v0, float& v1) {
    v0 = __uint_as_float(p << 16);
    v1 = __uint_as_float(p & 0xffff0000u);
}
__device__ __forceinline__ void split2(float v0, float v1, uint32_t& hi, uint32_t& lo) {
    hi = pack_bf16x2(v0, v1);
    float h0, h1; bf2_vals(hi, h0, h1);
    lo = pack_bf16x2(v0 - h0, v1 - h1);
}
__device__ __forceinline__ void mma16816(float* c, const uint32_t* a, uint32_t b0, uint32_t b1) {
    asm volatile("mma.sync.aligned.m16n8k16.row.col.f32.bf16.bf16.f32 "
                 "{%0,%1,%2,%3}, {%4,%5,%6,%7}, {%8,%9}, {%0,%1,%2,%3};"
                 : "+f"(c[0]), "+f"(c[1]), "+f"(c[2]), "+f"(c[3])
                 : "r"(a[0]), "r"(a[1]), "r"(a[2]), "r"(a[3]), "r"(b0), "r"(b1));
}
__device__ __forceinline__ void ldsm_x4(uint32_t* r, uint32_t addr) {
    asm volatile("ldmatrix.sync.aligned.m8n8.x4.shared.b16 {%0,%1,%2,%3}, [%4];"
                 : "=r"(r[0]), "=r"(r[1]), "=r"(r[2]), "=r"(r[3]) : "r"(addr));
}

__global__ __launch_bounds__(TB, 1)
void aniso_hmma_kernel(const float* __restrict__ x,  const float* __restrict__ r,
                       const float* __restrict__ W1, const float* __restrict__ b1,
                       const float* __restrict__ W2, const float* __restrict__ b2,
                       float* __restrict__ out)
{
    extern __shared__ char sm[];
    const uint32_t sbase = smem_u32(sm);
    float* srr = (float*)(sm + SM_RR);
    float* sb1 = (float*)(sm + SM_B1);
    float* sb2 = (float*)(sm + SM_B2);
    float* ses = (float*)(sm + SM_ES);

    const int tid  = threadIdx.x;
    const int wid  = tid >> 5;
    const int lane = tid & 31;
    const int g    = lane >> 2;
    const int t    = lane & 3;
    const size_t b0 = (size_t)blockIdx.x * ROWS;

    // ---- stage constants ----
    if (tid < NN) { srr[tid] = r[tid]; sb2[tid] = b2[tid]; }
    sb1[tid] = b1[tid];

    // ---- W1 -> bf16 hi/lo, [256][72] padded rows ----
    #pragma unroll 4
    for (int p = tid; p < HH * NN / 2; p += TB) {
        int h  = p >> 5;
        int n2 = (p & 31) * 2;
        float2 w = *(const float2*)(W1 + h * NN + n2);
        uint32_t hi, lo; split2(w.x, w.y, hi, lo);
        *(uint32_t*)(sm + SM_W1H + h * 144 + n2 * 2) = hi;
        *(uint32_t*)(sm + SM_W1L + h * 144 + n2 * 2) = lo;
    }
    // ---- W2 -> bf16 hi/lo, [64][264] padded rows ----
    #pragma unroll 4
    for (int p = tid; p < OO * HH / 2; p += TB) {
        int o  = p >> 7;
        int k2 = (p & 127) * 2;
        float2 w = *(const float2*)(W2 + o * HH + k2);
        uint32_t hi, lo; split2(w.x, w.y, hi, lo);
        *(uint32_t*)(sm + SM_W2H + o * 528 + k2 * 2) = hi;
        *(uint32_t*)(sm + SM_W2L + o * 528 + k2 * 2) = lo;
    }

    // ---- Newton solve + x_sphere conversion: every thread owns one row ----
    {
        float xv[NN];
        const float4* xr = (const float4*)(x + (b0 + tid) * NN);
        #pragma unroll
        for (int i = 0; i < NN / 4; i++) {
            float4 v = xr[i];
            xv[4*i] = v.x; xv[4*i+1] = v.y; xv[4*i+2] = v.z; xv[4*i+3] = v.w;
        }
        float s = 0.0f;
        #pragma unroll 1
        for (int it = 0; it < MAXIT; it++) {
            float m2s = -2.0f * s;
            float f0 = 0.0f, f1 = 0.0f, g0 = 0.0f, g1 = 0.0f;
            #pragma unroll
            for (int i = 0; i < NN; i += 2) {
                float r0 = srr[i], r1 = srr[i+1];
                float e0 = __expf(r0 * m2s), e1 = __expf(r1 * m2s);
                float p0 = e0 * xv[i] * xv[i], p1 = e1 * xv[i+1] * xv[i+1];
                f0 += p0;              f1 += p1;
                g0 = fmaf(r0, p0, g0); g1 = fmaf(r1, p1, g1);
            }
            float F = f0 + f1;
            float G = -2.0f * (g0 + g1);
            if (F < 1e-30f || G == 0.0f) break;       // all-zero row -> s = 0
            if (fabsf(F - 1.0f) < TOLV) break;        // ref's stop rule
            s -= __logf(F) * F / G;                   // Newton on ln F (monotone)
        }
        ses[tid] = __expf(s);                         // NU = 1
        #pragma unroll
        for (int i = 0; i < NN; i += 2) {
            float v0 = xv[i]   * __expf(-srr[i]   * s);
            float v1 = xv[i+1] * __expf(-srr[i+1] * s);
            uint32_t hi, lo; split2(v0, v1, hi, lo);
            *(uint32_t*)(sm + SM_XH + tid * 144 + i * 2) = hi;
            *(uint32_t*)(sm + SM_XL + tid * 144 + i * 2) = lo;
        }
    }
    __syncthreads();

    // ---- per-lane ldmatrix address offsets ----
    const uint32_t a_lo  = (uint32_t)((lane & 15) * 144 + (lane >> 4) * 16);
    const uint32_t w1_lo = (uint32_t)(((lane & 7) + ((lane >> 4) << 3)) * 144 + ((lane >> 3) & 1) * 16);
    const uint32_t w2_lo = (uint32_t)(((lane & 7) + ((lane >> 4) << 3)) * 528 + ((lane >> 3) & 1) * 16);

    #pragma unroll 1
    for (int half = 0; half < 2; half++) {
        const int rowb = wid * 32 + half * 16;
        const uint32_t xh_base = sbase + SM_XH + rowb * 144 + a_lo;
        const uint32_t xl_base = sbase + SM_XL + rowb * 144 + a_lo;

        float C2[8][4];
        #pragma unroll
        for (int nt = 0; nt < 8; nt++)
            { C2[nt][0] = 0.f; C2[nt][1] = 0.f; C2[nt][2] = 0.f; C2[nt][3] = 0.f; }

        #pragma unroll 1
        for (int hc = 0; hc < 4; hc++) {
            // ===== layer 1 chunk: C1[16x64] = Xs @ W1^T[:, hc*64..] =====
            float C1[8][4];
            #pragma unroll
            for (int nt = 0; nt < 8; nt++)
                { C1[nt][0] = 0.f; C1[nt][1] = 0.f; C1[nt][2] = 0.f; C1[nt][3] = 0.f; }

            #pragma unroll
            for (int ks = 0; ks < 4; ks++) {
                uint32_t ah[4], al[4];
                ldsm_x4(ah, xh_base + ks * 32);
                ldsm_x4(al, xl_base + ks * 32);
                const uint32_t w1b = sbase + SM_W1H + (hc * 64) * 144 + w1_lo + ks * 32;
                #pragma unroll
                for (int ntp = 0; ntp < 4; ntp++) {
                    uint32_t bh[4], bl[4];
                    ldsm_x4(bh, w1b + ntp * (16 * 144));
                    ldsm_x4(bl, w1b + ntp * (16 * 144) + D_W1LO);
                    mma16816(C1[2*ntp],   ah, bh[0], bh[1]);
                    mma16816(C1[2*ntp],   ah, bl[0], bl[1]);
                    mma16816(C1[2*ntp],   al, bh[0], bh[1]);
                    mma16816(C1[2*ntp+1], ah, bh[2], bh[3]);
                    mma16816(C1[2*ntp+1], ah, bl[2], bl[3]);
                    mma16816(C1[2*ntp+1], al, bh[2], bh[3]);
                }
            }

            // ===== epilogue 1 (registers): +b1, relu, bf16 split -> A2 frags =====
            uint32_t a2h[4][4], a2l[4][4];
            #pragma unroll
            for (int nt = 0; nt < 8; nt++) {
                const int colb = hc * 64 + nt * 8 + t * 2;
                float bb0 = sb1[colb], bb1 = sb1[colb + 1];
                float v0 = fmaxf(C1[nt][0] + bb0, 0.0f);
                float v1 = fmaxf(C1[nt][1] + bb1, 0.0f);
                float v2 = fmaxf(C1[nt][2] + bb0, 0.0f);
                float v3 = fmaxf(C1[nt][3] + bb1, 0.0f);
                const int ks = nt >> 1, q = (nt & 1) * 2;
                split2(v0, v1, a2h[ks][q],     a2l[ks][q]);
                split2(v2, v3, a2h[ks][q + 1], a2l[ks][q + 1]);
            }

            // ===== layer 2 chunk: C2 += H @ W2^T[hc*64.., :] =====
            #pragma unroll
            for (int ks = 0; ks < 4; ks++) {
                const uint32_t w2b = sbase + SM_W2H + w2_lo + hc * 128 + ks * 32;
                #pragma unroll
                for (int ntp = 0; ntp < 4; ntp++) {
                    uint32_t bh[4], bl[4];
                    ldsm_x4(bh, w2b + ntp * (16 * 528));
                    ldsm_x4(bl, w2b + ntp * (16 * 528) + D_W2LO);
                    mma16816(C2[2*ntp],   a2h[ks], bh[0], bh[1]);
                    mma16816(C2[2*ntp],   a2h[ks], bl[0], bl[1]);
                    mma16816(C2[2*ntp],   a2l[ks], bh[0], bh[1]);
                    mma16816(C2[2*ntp+1], a2h[ks], bh[2], bh[3]);
                    mma16816(C2[2*ntp+1], a2h[ks], bl[2], bl[3]);
                    mma16816(C2[2*ntp+1], a2l[ks], bh[2], bh[3]);
                }
            }
        }

        // ---- epilogue 2: (+b2) * e^s ----
        const float es0 = ses[rowb + g];
        const float es1 = ses[rowb + g + 8];
        float* o0r = out + (b0 + rowb + g) * OO;
        float* o1r = out + (b0 + rowb + g + 8) * OO;
        #pragma unroll
        for (int nt = 0; nt < 8; nt++) {
            const int col = nt * 8 + t * 2;
            float bb0 = sb2[col], bb1 = sb2[col + 1];
            float2 u0, u1;
            u0.x = (C2[nt][0] + bb0) * es0;  u0.y = (C2[nt][1] + bb1) * es0;
            u1.x = (C2[nt][2] + bb0) * es1;  u1.y = (C2[nt][3] + bb1) * es1;
            *(float2*)(o0r + col) = u0;
            *(float2*)(o1r + col) = u1;
        }
    }
}

extern "C" void kernel_launch(void* const* d_in, const int* in_sizes, int n_in,
                              void* d_out, int out_size)
{
    const float* x  = (const float*)d_in[0];
    const float* r  = (const float*)d_in[1];
    const float* W1 = (const float*)d_in[2];
    const float* b1 = (const float*)d_in[3];
    const float* W2 = (const float*)d_in[4];
    const float* b2 = (const float*)d_in[5];
    float* out = (float*)d_out;

    const int B = in_sizes[0] / NN;          // 262144
    cudaFuncSetAttribute(aniso_hmma_kernel,
                         cudaFuncAttributeMaxDynamicSharedMemorySize, SM_TOTAL);
    aniso_hmma_kernel<<<B / ROWS, TB, SM_TOTAL>>>(x, r, W1, b1, W2, b2, out);
}

// round 11
// speedup vs baseline: 1.9630x; 1.3994x over previous
#include <cuda_runtime.h>
#include <cuda_fp16.h>
#include <cstdint>

#define NN      64
#define HH      256
#define OO      64
#define MAXIT   30
#define TOLV    1e-7f

#define TB      256          // 8 warps: 0-3 solve, 4-7 weight-convert; all 8 in mainloop
#define ROWS    128          // samples per block; one 16-row tile per warp

// ---- smem byte layout (fp16 planes; padded strides keep LDSM conflict-free) ----
// X  : [128 rows][72 f16] hi/lo  stride 144B (36 words ≡ 4 mod 32)
// W1 : [256 rows][72 f16]        row n = W1[n][0..63]
// W2 : [64 rows][264 f16]        row n = W2[n][0..255], stride 528B (132 ≡ 4)
#define SM_XH   0
#define SM_XL   (SM_XH + ROWS*144)        // 18432
#define SM_W1   (SM_XL + ROWS*144)        // 36864
#define SM_W2   (SM_W1 + 256*144)         // 73728
#define SM_RR   (SM_W2 + 64*528)          // 107520  r[64] f32
#define SM_B1   (SM_RR + 256)             // 107776  b1[256] f32
#define SM_B2   (SM_B1 + 1024)            // 108800  b2[64] f32
#define SM_ES   (SM_B2 + 256)             // 109056  es[128] f32
#define SM_TOTAL (SM_ES + 512)            // 109568 bytes (~107 KB -> 2 blocks/SM)

__device__ __forceinline__ uint32_t smem_u32(const void* p) {
    uint32_t a;
    asm("{ .reg .u64 t; cvta.to.shared.u64 t, %1; cvt.u32.u64 %0, t; }" : "=r"(a) : "l"(p));
    return a;
}
// fp16 hi/lo split of a value pair -> packed f16x2 words (v0 in low half)
__device__ __forceinline__ void split2h(float v0, float v1, uint32_t& hi, uint32_t& lo) {
    __half2 h = __floats2half2_rn(v0, v1);
    float2 hf = __half22float2(h);
    __half2 l = __floats2half2_rn(v0 - hf.x, v1 - hf.y);
    hi = *reinterpret_cast<uint32_t*>(&h);
    lo = *reinterpret_cast<uint32_t*>(&l);
}
__device__ __forceinline__ uint32_t packh2(float v0, float v1) {
    __half2 h = __floats2half2_rn(v0, v1);
    return *reinterpret_cast<uint32_t*>(&h);
}
__device__ __forceinline__ void mma16816(float* c, const uint32_t* a, uint32_t b0, uint32_t b1) {
    asm volatile("mma.sync.aligned.m16n8k16.row.col.f32.f16.f16.f32 "
                 "{%0,%1,%2,%3}, {%4,%5,%6,%7}, {%8,%9}, {%0,%1,%2,%3};"
                 : "+f"(c[0]), "+f"(c[1]), "+f"(c[2]), "+f"(c[3])
                 : "r"(a[0]), "r"(a[1]), "r"(a[2]), "r"(a[3]), "r"(b0), "r"(b1));
}
__device__ __forceinline__ void ldsm_x4(uint32_t* r, uint32_t addr) {
    asm volatile("ldmatrix.sync.aligned.m8n8.x4.shared.b16 {%0,%1,%2,%3}, [%4];"
                 : "=r"(r[0]), "=r"(r[1]), "=r"(r[2]), "=r"(r[3]) : "r"(addr));
}

__global__ __launch_bounds__(TB, 2)
void aniso_hmma_kernel(const float* __restrict__ x,  const float* __restrict__ r,
                       const float* __restrict__ W1, const float* __restrict__ b1,
                       const float* __restrict__ W2, const float* __restrict__ b2,
                       float* __restrict__ out)
{
    extern __shared__ char sm[];
    const uint32_t sbase = smem_u32(sm);
    float* srr = (float*)(sm + SM_RR);
    float* sb1 = (float*)(sm + SM_B1);
    float* sb2 = (float*)(sm + SM_B2);
    float* ses = (float*)(sm + SM_ES);

    const int tid  = threadIdx.x;
    const int wid  = tid >> 5;
    const int lane = tid & 31;
    const int g    = lane >> 2;
    const int t    = lane & 3;
    const size_t b0 = (size_t)blockIdx.x * ROWS;

    if (tid < NN) srr[tid] = r[tid];
    __syncthreads();

    if (tid < ROWS) {
        // ===== warps 0-3: Newton solve (1 row/thread) + x_sphere fp16 split =====
        const float* xr = x + (b0 + tid) * NN;
        float la[NN];
        {
            const float4* x4 = (const float4*)xr;
            #pragma unroll
            for (int i = 0; i < NN / 4; i++) {
                float4 v = x4[i];
                la[4*i]   = __logf(v.x * v.x);
                la[4*i+1] = __logf(v.y * v.y);
                la[4*i+2] = __logf(v.z * v.z);
                la[4*i+3] = __logf(v.w * v.w);
            }
        }
        float s = 0.0f;
        #pragma unroll 1
        for (int it = 0; it < MAXIT; it++) {
            const float m2s = -2.0f * s;
            float f0 = 0.0f, f1 = 0.0f, g0 = 0.0f, g1 = 0.0f;
            #pragma unroll
            for (int i = 0; i < NN; i += 2) {
                float r0 = srr[i], r1 = srr[i+1];
                float p0 = __expf(fmaf(r0, m2s, la[i]));
                float p1 = __expf(fmaf(r1, m2s, la[i+1]));
                f0 += p0;              f1 += p1;
                g0 = fmaf(r0, p0, g0); g1 = fmaf(r1, p1, g1);
            }
            float F = f0 + f1;
            float G = -2.0f * (g0 + g1);
            if (F < 1e-30f || G == 0.0f) break;        // all-zero row -> s = 0
            if (fabsf(F - 1.0f) < TOLV) break;         // ref's stop rule
            float step = __logf(F) * F / G;            // Newton on ln F (convex)
            s -= step;
            if (fabsf(step) < 3e-6f) break;            // float-noise floor guard
        }
        ses[tid] = __expf(s);                          // NU = 1
        {
            const float4* x4 = (const float4*)xr;      // reload (L2-hot)
            #pragma unroll
            for (int i = 0; i < NN / 4; i++) {
                float4 v = x4[i];
                float e0 = __expf(-srr[4*i]   * s), e1 = __expf(-srr[4*i+1] * s);
                float e2 = __expf(-srr[4*i+2] * s), e3 = __expf(-srr[4*i+3] * s);
                uint32_t h0, l0, h1, l1;
                split2h(v.x * e0, v.y * e1, h0, l0);
                split2h(v.z * e2, v.w * e3, h1, l1);
                *(uint32_t*)(sm + SM_XH + tid * 144 + i * 8)     = h0;
                *(uint32_t*)(sm + SM_XH + tid * 144 + i * 8 + 4) = h1;
                *(uint32_t*)(sm + SM_XL + tid * 144 + i * 8)     = l0;
                *(uint32_t*)(sm + SM_XL + tid * 144 + i * 8 + 4) = l1;
            }
        }
    } else {
        // ===== warps 4-7: weight conversion to fp16 (runs concurrently) =====
        const int u = tid - ROWS;   // 0..127
        #pragma unroll 4
        for (int p = u; p < HH * NN / 2; p += 128) {
            int h  = p >> 5;
            int n2 = (p & 31) * 2;
            float2 w = *(const float2*)(W1 + h * NN + n2);
            *(uint32_t*)(sm + SM_W1 + h * 144 + n2 * 2) = packh2(w.x, w.y);
        }
        #pragma unroll 4
        for (int p = u; p < OO * HH / 2; p += 128) {
            int o  = p >> 7;
            int k2 = (p & 127) * 2;
            float2 w = *(const float2*)(W2 + o * HH + k2);
            *(uint32_t*)(sm + SM_W2 + o * 528 + k2 * 2) = packh2(w.x, w.y);
        }
        sb1[u] = b1[u];
        sb1[u + 128] = b1[u + 128];
        if (u < OO) sb2[u] = b2[u];
    }
    __syncthreads();

    // ---- per-lane ldmatrix address offsets ----
    const uint32_t a_lo  = (uint32_t)((lane & 15) * 144 + (lane >> 4) * 16);
    const uint32_t w1_lo = (uint32_t)(((lane & 7) + ((lane >> 4) << 3)) * 144 + ((lane >> 3) & 1) * 16);
    const uint32_t w2_lo = (uint32_t)(((lane & 7) + ((lane >> 4) << 3)) * 528 + ((lane >> 3) & 1) * 16);

    const int rowb = wid * 16;
    const uint32_t xh_base = sbase + SM_XH + rowb * 144 + a_lo;
    const uint32_t xl_base = sbase + SM_XL + rowb * 144 + a_lo;

    float C2[8][4];
    #pragma unroll
    for (int nt = 0; nt < 8; nt++)
        { C2[nt][0] = 0.f; C2[nt][1] = 0.f; C2[nt][2] = 0.f; C2[nt][3] = 0.f; }

    #pragma unroll 1
    for (int hc = 0; hc < 4; hc++) {
        // ===== layer 1 chunk: C1[16x64] = (Xh+Xl) @ W1^T[:, hc*64..] =====
        float C1[8][4];
        #pragma unroll
        for (int nt = 0; nt < 8; nt++)
            { C1[nt][0] = 0.f; C1[nt][1] = 0.f; C1[nt][2] = 0.f; C1[nt][3] = 0.f; }

        #pragma unroll
        for (int ks = 0; ks < 4; ks++) {
            uint32_t ah[4], al[4];
            ldsm_x4(ah, xh_base + ks * 32);
            ldsm_x4(al, xl_base + ks * 32);
            const uint32_t w1b = sbase + SM_W1 + (hc * 64) * 144 + w1_lo + ks * 32;
            #pragma unroll
            for (int ntp = 0; ntp < 4; ntp++) {
                uint32_t bh[4];
                ldsm_x4(bh, w1b + ntp * (16 * 144));
                mma16816(C1[2*ntp],   ah, bh[0], bh[1]);
                mma16816(C1[2*ntp],   al, bh[0], bh[1]);
                mma16816(C1[2*ntp+1], ah, bh[2], bh[3]);
                mma16816(C1[2*ntp+1], al, bh[2], bh[3]);
            }
        }

        // ===== epilogue 1 (registers): +b1, relu, fp16 split -> A2 frags =====
        uint32_t a2h[4][4], a2l[4][4];
        #pragma unroll
        for (int nt = 0; nt < 8; nt++) {
            const int colb = hc * 64 + nt * 8 + t * 2;
            float bb0 = sb1[colb], bb1 = sb1[colb + 1];
            float v0 = fmaxf(C1[nt][0] + bb0, 0.0f);
            float v1 = fmaxf(C1[nt][1] + bb1, 0.0f);
            float v2 = fmaxf(C1[nt][2] + bb0, 0.0f);
            float v3 = fmaxf(C1[nt][3] + bb1, 0.0f);
            const int ks = nt >> 1, q = (nt & 1) * 2;
            split2h(v0, v1, a2h[ks][q],     a2l[ks][q]);
            split2h(v2, v3, a2h[ks][q + 1], a2l[ks][q + 1]);
        }

        // ===== layer 2 chunk: C2 += (A2h+A2l) @ W2^T[hc*64.., :] =====
        #pragma unroll
        for (int ks = 0; ks < 4; ks++) {
            const uint32_t w2b = sbase + SM_W2 + w2_lo + hc * 128 + ks * 32;
            #pragma unroll
            for (int ntp = 0; ntp < 4; ntp++) {
                uint32_t bh[4];
                ldsm_x4(bh, w2b + ntp * (16 * 528));
                mma16816(C2[2*ntp],   a2h[ks], bh[0], bh[1]);
                mma16816(C2[2*ntp],   a2l[ks], bh[0], bh[1]);
                mma16816(C2[2*ntp+1], a2h[ks], bh[2], bh[3]);
                mma16816(C2[2*ntp+1], a2l[ks], bh[2], bh[3]);
            }
        }
    }

    // ---- epilogue 2: (+b2) * e^s ----
    const float es0 = ses[rowb + g];
    const float es1 = ses[rowb + g + 8];
    float* o0r = out + (b0 + rowb + g) * OO;
    float* o1r = out + (b0 + rowb + g + 8) * OO;
    #pragma unroll
    for (int nt = 0; nt < 8; nt++) {
        const int col = nt * 8 + t * 2;
        float bb0 = sb2[col], bb1 = sb2[col + 1];
        float2 u0, u1;
        u0.x = (C2[nt][0] + bb0) * es0;  u0.y = (C2[nt][1] + bb1) * es0;
        u1.x = (C2[nt][2] + bb0) * es1;  u1.y = (C2[nt][3] + bb1) * es1;
        *(float2*)(o0r + col) = u0;
        *(float2*)(o1r + col) = u1;
    }
}

extern "C" void kernel_launch(void* const* d_in, const int* in_sizes, int n_in,
                              void* d_out, int out_size)
{
    const float* x  = (const float*)d_in[0];
    const float* r  = (const float*)d_in[1];
    const float* W1 = (const float*)d_in[2];
    const float* b1 = (const float*)d_in[3];
    const float* W2 = (const float*)d_in[4];
    const float* b2 = (const float*)d_in[5];
    float* out = (float*)d_out;

    const int B = in_sizes[0] / NN;          // 262144
    cudaFuncSetAttribute(aniso_hmma_kernel,
                         cudaFuncAttributeMaxDynamicSharedMemorySize, SM_TOTAL);
    aniso_hmma_kernel<<<B / ROWS, TB, SM_TOTAL>>>(x, r, W1, b1, W2, b2, out);
}

// round 17
// speedup vs baseline: 1.9688x; 1.0029x over previous
#include <cuda_runtime.h>
#include <cuda_fp16.h>
#include <cstdint>

#define NN      64
#define HH      256
#define OO      64
#define MAXIT   30
#define TOLV    1e-7f

#define TB      256          // 8 warps: 0-3 solve, 4-7 weight-convert; all 8 in mainloop
#define ROWS    128          // samples per block; one 16-row tile per warp

// ---- smem byte layout (fp16 planes; padded strides keep LDSM conflict-free) ----
#define SM_XH   0
#define SM_XL   (SM_XH + ROWS*144)        // 18432
#define SM_W1   (SM_XL + ROWS*144)        // 36864
#define SM_W2   (SM_W1 + 256*144)         // 73728
#define SM_RR   (SM_W2 + 64*528)          // 107520  r[64] f32
#define SM_B1   (SM_RR + 256)             // 107776  b1[256] f32
#define SM_B2   (SM_B1 + 1024)            // 108800  b2[64] f32
#define SM_ES   (SM_B2 + 256)             // 109056  es[128] f32
#define SM_TOTAL (SM_ES + 512)            // 109568 bytes (~107 KB -> 2 blocks/SM)

__device__ __forceinline__ uint32_t smem_u32(const void* p) {
    uint32_t a;
    asm("{ .reg .u64 t; cvta.to.shared.u64 t, %1; cvt.u32.u64 %0, t; }" : "=r"(a) : "l"(p));
    return a;
}
__device__ __forceinline__ void split2h(float v0, float v1, uint32_t& hi, uint32_t& lo) {
    __half2 h = __floats2half2_rn(v0, v1);
    float2 hf = __half22float2(h);
    __half2 l = __floats2half2_rn(v0 - hf.x, v1 - hf.y);
    hi = *reinterpret_cast<uint32_t*>(&h);
    lo = *reinterpret_cast<uint32_t*>(&l);
}
__device__ __forceinline__ uint32_t packh2(float v0, float v1) {
    __half2 h = __floats2half2_rn(v0, v1);
    return *reinterpret_cast<uint32_t*>(&h);
}
__device__ __forceinline__ void mma16816(float* c, const uint32_t* a, uint32_t b0, uint32_t b1) {
    asm volatile("mma.sync.aligned.m16n8k16.row.col.f32.f16.f16.f32 "
                 "{%0,%1,%2,%3}, {%4,%5,%6,%7}, {%8,%9}, {%0,%1,%2,%3};"
                 : "+f"(c[0]), "+f"(c[1]), "+f"(c[2]), "+f"(c[3])
                 : "r"(a[0]), "r"(a[1]), "r"(a[2]), "r"(a[3]), "r"(b0), "r"(b1));
}
__device__ __forceinline__ void ldsm_x4(uint32_t* r, uint32_t addr) {
    asm volatile("ldmatrix.sync.aligned.m8n8.x4.shared.b16 {%0,%1,%2,%3}, [%4];"
                 : "=r"(r[0]), "=r"(r[1]), "=r"(r[2]), "=r"(r[3]) : "r"(addr));
}

__global__ __launch_bounds__(TB, 2)
void aniso_hmma_kernel(const float* __restrict__ x,  const float* __restrict__ r,
                       const float* __restrict__ W1, const float* __restrict__ b1,
                       const float* __restrict__ W2, const float* __restrict__ b2,
                       float* __restrict__ out)
{
    extern __shared__ char sm[];
    const uint32_t sbase = smem_u32(sm);
    float* srr = (float*)(sm + SM_RR);
    float* sb1 = (float*)(sm + SM_B1);
    float* sb2 = (float*)(sm + SM_B2);
    float* ses = (float*)(sm + SM_ES);

    const int tid  = threadIdx.x;
    const int wid  = tid >> 5;
    const int lane = tid & 31;
    const int g    = lane >> 2;
    const int t    = lane & 3;
    const size_t b0 = (size_t)blockIdx.x * ROWS;

    if (tid < NN) srr[tid] = r[tid];
    __syncthreads();

    if (tid < ROWS) {
        // ===== warps 0-3: Newton solve (1 row/thread) + x_sphere fp16 split =====
        const float* xr = x + (b0 + tid) * NN;
        float la[NN];
        {
            const float4* x4 = (const float4*)xr;
            #pragma unroll
            for (int i = 0; i < NN / 4; i++) {
                float4 v = x4[i];
                la[4*i]   = __logf(v.x * v.x);
                la[4*i+1] = __logf(v.y * v.y);
                la[4*i+2] = __logf(v.z * v.z);
                la[4*i+3] = __logf(v.w * v.w);
            }
        }
        float s = 0.0f;
        #pragma unroll 1
        for (int it = 0; it < MAXIT; it++) {
            const float m2s = -2.0f * s;
            float f0 = 0.0f, f1 = 0.0f, g0 = 0.0f, g1 = 0.0f;
            #pragma unroll
            for (int i = 0; i < NN; i += 2) {
                float r0 = srr[i], r1 = srr[i+1];
                float p0 = __expf(fmaf(r0, m2s, la[i]));
                float p1 = __expf(fmaf(r1, m2s, la[i+1]));
                f0 += p0;              f1 += p1;
                g0 = fmaf(r0, p0, g0); g1 = fmaf(r1, p1, g1);
            }
            float F = f0 + f1;
            float G = -2.0f * (g0 + g1);
            if (F < 1e-30f || G == 0.0f) break;        // all-zero row -> s = 0
            if (fabsf(F - 1.0f) < TOLV) break;         // ref's stop rule
            float step = __logf(F) * F / G;            // Newton on ln F (convex)
            s -= step;
            if (fabsf(step) < 3e-6f) break;            // float-noise floor guard
        }
        ses[tid] = __expf(s);                          // NU = 1
        {
            const float4* x4 = (const float4*)xr;      // reload (L2-hot)
            #pragma unroll
            for (int i = 0; i < NN / 4; i++) {
                float4 v = x4[i];
                float e0 = __expf(-srr[4*i]   * s), e1 = __expf(-srr[4*i+1] * s);
                float e2 = __expf(-srr[4*i+2] * s), e3 = __expf(-srr[4*i+3] * s);
                uint32_t h0, l0, h1, l1;
                split2h(v.x * e0, v.y * e1, h0, l0);
                split2h(v.z * e2, v.w * e3, h1, l1);
                *(uint32_t*)(sm + SM_XH + tid * 144 + i * 8)     = h0;
                *(uint32_t*)(sm + SM_XH + tid * 144 + i * 8 + 4) = h1;
                *(uint32_t*)(sm + SM_XL + tid * 144 + i * 8)     = l0;
                *(uint32_t*)(sm + SM_XL + tid * 144 + i * 8 + 4) = l1;
            }
        }
    } else {
        // ===== warps 4-7: weight conversion to fp16 (runs concurrently) =====
        const int u = tid - ROWS;   // 0..127
        #pragma unroll 4
        for (int p = u; p < HH * NN / 2; p += 128) {
            int h  = p >> 5;
            int n2 = (p & 31) * 2;
            float2 w = *(const float2*)(W1 + h * NN + n2);
            *(uint32_t*)(sm + SM_W1 + h * 144 + n2 * 2) = packh2(w.x, w.y);
        }
        #pragma unroll 4
        for (int p = u; p < OO * HH / 2; p += 128) {
            int o  = p >> 7;
            int k2 = (p & 127) * 2;
            float2 w = *(const float2*)(W2 + o * HH + k2);
            *(uint32_t*)(sm + SM_W2 + o * 528 + k2 * 2) = packh2(w.x, w.y);
        }
        sb1[u] = b1[u];
        sb1[u + 128] = b1[u + 128];
        if (u < OO) sb2[u] = b2[u];
    }
    __syncthreads();

    // ---- per-lane ldmatrix address offsets ----
    const uint32_t a_lo  = (uint32_t)((lane & 15) * 144 + (lane >> 4) * 16);
    const uint32_t w1_lo = (uint32_t)(((lane & 7) + ((lane >> 4) << 3)) * 144 + ((lane >> 3) & 1) * 16);
    const uint32_t w2_lo = (uint32_t)(((lane & 7) + ((lane >> 4) << 3)) * 528 + ((lane >> 3) & 1) * 16);

    const int rowb = wid * 16;
    const uint32_t xh_base = sbase + SM_XH + rowb * 144 + a_lo;
    const uint32_t xl_base = sbase + SM_XL + rowb * 144 + a_lo;

    float C2[8][4];
    #pragma unroll
    for (int nt = 0; nt < 8; nt++)
        { C2[nt][0] = 0.f; C2[nt][1] = 0.f; C2[nt][2] = 0.f; C2[nt][3] = 0.f; }

    #pragma unroll 1
    for (int hc = 0; hc < 4; hc++) {
        // ===== layer 1 chunk: C1[16x64] = (Xh+Xl) @ W1^T[:, hc*64..] =====
        float C1[8][4];
        #pragma unroll
        for (int nt = 0; nt < 8; nt++)
            { C1[nt][0] = 0.f; C1[nt][1] = 0.f; C1[nt][2] = 0.f; C1[nt][3] = 0.f; }

        #pragma unroll
        for (int ks = 0; ks < 4; ks++) {
            uint32_t ah[4], al[4];
            ldsm_x4(ah, xh_base + ks * 32);
            ldsm_x4(al, xl_base + ks * 32);
            const uint32_t w1b = sbase + SM_W1 + (hc * 64) * 144 + w1_lo + ks * 32;
            uint32_t bh[4][4];
            #pragma unroll
            for (int ntp = 0; ntp < 4; ntp++)
                ldsm_x4(bh[ntp], w1b + ntp * (16 * 144));
            // ah pass over all 8 accumulators (RAW distance 8)
            #pragma unroll
            for (int ntp = 0; ntp < 4; ntp++) {
                mma16816(C1[2*ntp],   ah, bh[ntp][0], bh[ntp][1]);
                mma16816(C1[2*ntp+1], ah, bh[ntp][2], bh[ntp][3]);
            }
            // al pass
            #pragma unroll
            for (int ntp = 0; ntp < 4; ntp++) {
                mma16816(C1[2*ntp],   al, bh[ntp][0], bh[ntp][1]);
                mma16816(C1[2*ntp+1], al, bh[ntp][2], bh[ntp][3]);
            }
        }

        // ===== epilogue 1 (registers): +b1, relu, fp16 split -> A2 frags =====
        uint32_t a2h[4][4], a2l[4][4];
        #pragma unroll
        for (int nt = 0; nt < 8; nt++) {
            const int colb = hc * 64 + nt * 8 + t * 2;
            float bb0 = sb1[colb], bb1 = sb1[colb + 1];
            float v0 = fmaxf(C1[nt][0] + bb0, 0.0f);
            float v1 = fmaxf(C1[nt][1] + bb1, 0.0f);
            float v2 = fmaxf(C1[nt][2] + bb0, 0.0f);
            float v3 = fmaxf(C1[nt][3] + bb1, 0.0f);
            const int ks = nt >> 1, q = (nt & 1) * 2;
            split2h(v0, v1, a2h[ks][q],     a2l[ks][q]);
            split2h(v2, v3, a2h[ks][q + 1], a2l[ks][q + 1]);
        }

        // ===== layer 2 chunk: C2 += (A2h+A2l) @ W2^T[hc*64.., :] =====
        #pragma unroll
        for (int ks = 0; ks < 4; ks++) {
            const uint32_t w2b = sbase + SM_W2 + w2_lo + hc * 128 + ks * 32;
            uint32_t bh[4][4];
            #pragma unroll
            for (int ntp = 0; ntp < 4; ntp++)
                ldsm_x4(bh[ntp], w2b + ntp * (16 * 528));
            #pragma unroll
            for (int ntp = 0; ntp < 4; ntp++) {
                mma16816(C2[2*ntp],   a2h[ks], bh[ntp][0], bh[ntp][1]);
                mma16816(C2[2*ntp+1], a2h[ks], bh[ntp][2], bh[ntp][3]);
            }
            #pragma unroll
            for (int ntp = 0; ntp < 4; ntp++) {
                mma16816(C2[2*ntp],   a2l[ks], bh[ntp][0], bh[ntp][1]);
                mma16816(C2[2*ntp+1], a2l[ks], bh[ntp][2], bh[ntp][3]);
            }
        }
    }

    // ---- epilogue 2: (+b2) * e^s ----
    const float es0 = ses[rowb + g];
    const float es1 = ses[rowb + g + 8];
    float* o0r = out + (b0 + rowb + g) * OO;
    float* o1r = out + (b0 + rowb + g + 8) * OO;
    #pragma unroll
    for (int nt = 0; nt < 8; nt++) {
        const int col = nt * 8 + t * 2;
        float bb0 = sb2[col], bb1 = sb2[col + 1];
        float2 u0, u1;
        u0.x = (C2[nt][0] + bb0) * es0;  u0.y = (C2[nt][1] + bb1) * es0;
        u1.x = (C2[nt][2] + bb0) * es1;  u1.y = (C2[nt][3] + bb1) * es1;
        *(float2*)(o0r + col) = u0;
        *(float2*)(o1r + col) = u1;
    }
}

extern "C" void kernel_launch(void* const* d_in, const int* in_sizes, int n_in,
                              void* d_out, int out_size)
{
    const float* x  = (const float*)d_in[0];
    const float* r  = (const float*)d_in[1];
    const float* W1 = (const float*)d_in[2];
    const float* b1 = (const float*)d_in[3];
    const float* W2 = (const float*)d_in[4];
    const float* b2 = (const float*)d_in[5];
    float* out = (float*)d_out;

    const int B = in_sizes[0] / NN;          // 262144
    cudaFuncSetAttribute(aniso_hmma_kernel,
                         cudaFuncAttributeMaxDynamicSharedMemorySize, SM_TOTAL);
    aniso_hmma_kernel<<<B / ROWS, TB, SM_TOTAL>>>(x, r, W1, b1, W2, b2, out);
}